// round 10
// baseline (speedup 1.0000x reference)
#include <cuda_runtime.h>
#include <cstdint>

// ---------------------------------------------------------------------------
// GCN_8796093022507: 2-layer GCN collapsed to scalar edge aggregations.
// Dropout = JAX threefry2x32 partitionable path: bits(i) = o0^o1 of
// tf(key,(0,i)); foldlike split: key_j = tf(parent,(0,j)).
// R9: RNG masks computed in a dedicated kernel on a SECOND STREAM,
// concurrent with the memory-bound degree pass (fork/join via events,
// graph-capturable). deg reverted to lean 32-reg form.
// ---------------------------------------------------------------------------

#define MAXN 100352
#define KEEP_TH 0x66666800u   // bits < TH  <=>  uniform(bits) < 0.4f
#define INV_KEEP 2.5f         // 1/(1-0.6)

__device__ int      g_deg[MAXN];
__device__ float    g_dinv[MAXN];
__device__ float    g_p1[MAXN];
__device__ float    g_acc1[MAXN];
__device__ float    g_p2[MAXN];
__device__ float    g_acc2[MAXN];
__device__ unsigned g_mask1[MAXN / 32 + 2];   // dropout1 keep bits, node n -> bit n
__device__ unsigned g_mask2[MAXN / 2 + 2];    // dropout2 keep bits, element 16n+c
__device__ int      g_is64;

__host__ __device__ __forceinline__ uint32_t rotl32(uint32_t v, int r) {
#ifdef __CUDA_ARCH__
    return __funnelshift_l(v, v, r);
#else
    return (v << r) | (v >> (32 - r));
#endif
}

__host__ __device__ __forceinline__ void tf2x32(uint32_t k0, uint32_t k1,
                                                uint32_t x0, uint32_t x1,
                                                uint32_t& o0, uint32_t& o1) {
    const uint32_t k2 = k0 ^ k1 ^ 0x1BD11BDAu;
    x0 += k0; x1 += k1;
#define TFR(r) { x0 += x1; x1 = rotl32(x1, r); x1 ^= x0; }
    TFR(13) TFR(15) TFR(26) TFR(6)
    x0 += k1; x1 += k2 + 1u;
    TFR(17) TFR(29) TFR(16) TFR(24)
    x0 += k2; x1 += k0 + 2u;
    TFR(13) TFR(15) TFR(26) TFR(6)
    x0 += k0; x1 += k1 + 3u;
    TFR(17) TFR(29) TFR(16) TFR(24)
    x0 += k1; x1 += k2 + 4u;
    TFR(13) TFR(15) TFR(26) TFR(6)
    o0 = x0 + k2; o1 = x1 + k0 + 5u;
#undef TFR
}

__device__ __forceinline__ uint32_t rbits32(uint32_t k0, uint32_t k1, uint32_t i) {
    uint32_t o0, o1;
    tf2x32(k0, k1, 0u, i, o0, o1);
    return o0 ^ o1;
}

// ---------------------------------------------------------------------------
// K0: zero scratch; detect index dtype (int64 <=> all odd 32-bit words zero).
__global__ void k_init(const unsigned int* __restrict__ ei32, int N, long long nwords) {
    int i = blockIdx.x * blockDim.x + threadIdx.x;
    int stride = gridDim.x * blockDim.x;
    for (int n = i; n < N; n += stride) {
        g_deg[n] = 0; g_acc1[n] = 0.f; g_acc2[n] = 0.f;
    }
    if (blockIdx.x == 0) {
        unsigned int v = 0;
        #pragma unroll
        for (int k = 0; k < 8; k++) {
            long long w = 1 + 2LL * (threadIdx.x * 8 + k);
            if (w < nwords) v |= ei32[w];
        }
        int nz = __syncthreads_or(v != 0);
        if (threadIdx.x == 0) g_is64 = nz ? 0 : 1;
    }
}

// ---------------------------------------------------------------------------
// K_RNG (second stream): all dropout masks.
//   mask2: warp gw covers elements [64gw, 64gw+64): lane l -> 64gw+l and
//          64gw+32+l; two ballots = words 2gw, 2gw+1 (element e -> bit e&31).
//   mask1: lane l of warp gw -> node 32gw+l -> word gw.
__global__ void __launch_bounds__(256) k_rng(int N,
                                             uint32_t k1a, uint32_t k1b,
                                             uint32_t k2a, uint32_t k2b) {
    long long t = blockIdx.x * (long long)blockDim.x + threadIdx.x;
    int lane = threadIdx.x & 31;
    long long wbase = (t - lane) * 2;    // 64 * global_warp_id
    long long TE = 16LL * N;
    long long e0 = wbase + lane, e1 = wbase + 32 + lane;
    bool kp0 = (e0 < TE) && rbits32(k2a, k2b, (uint32_t)e0) < KEEP_TH;
    bool kp1 = (e1 < TE) && rbits32(k2a, k2b, (uint32_t)e1) < KEEP_TH;
    unsigned w0 = __ballot_sync(0xFFFFFFFFu, kp0);
    unsigned w1 = __ballot_sync(0xFFFFFFFFu, kp1);
    bool kpn = (t < N) && rbits32(k1a, k1b, (uint32_t)t) < KEEP_TH;
    unsigned wn = __ballot_sync(0xFFFFFFFFu, kpn);
    if (lane == 0) {
        if (wbase < TE)      g_mask2[(int)(wbase >> 5)]     = w0;
        if (wbase + 32 < TE) g_mask2[(int)(wbase >> 5) + 1] = w1;
        if (t < N)           g_mask1[(int)(t >> 5)]         = wn;
    }
}

// ---------------------------------------------------------------------------
// Load 8 consecutive indices at element offset `off` (8-aligned).
__device__ __forceinline__ void load8(const void* eiv, long long off, int is64,
                                      int* out) {
    if (is64) {
        const longlong2* e = (const longlong2*)((const long long*)eiv + off);
        #pragma unroll
        for (int k = 0; k < 4; k++) {
            longlong2 d = e[k];
            out[2 * k] = (int)d.x; out[2 * k + 1] = (int)d.y;
        }
    } else {
        const int4* e = (const int4*)((const int*)eiv + off);
        int4 a = e[0], b = e[1];
        out[0] = a.x; out[1] = a.y; out[2] = a.z; out[3] = a.w;
        out[4] = b.x; out[5] = b.y; out[6] = b.z; out[7] = b.w;
    }
}

// ---------------------------------------------------------------------------
// K1: in-degree at dst. 8 edges/thread (lean, concurrent with k_rng).
__global__ void __launch_bounds__(256) k_deg(const void* __restrict__ eiv, long long E) {
    long long base = 8LL * (blockIdx.x * (long long)blockDim.x + threadIdx.x);
    if (base >= E) return;
    int is64 = g_is64;
    if (base + 8 <= E) {
        int dsts[8];
        load8(eiv, E + base, is64, dsts);
        #pragma unroll
        for (int i = 0; i < 8; i++) atomicAdd(&g_deg[dsts[i]], 1);
    } else {
        int n = (int)(E - base);
        if (is64) {
            const long long* e = (const long long*)eiv;
            for (int i = 0; i < n; i++) atomicAdd(&g_deg[(int)e[E + base + i]], 1);
        } else {
            const int* e = (const int*)eiv;
            for (int i = 0; i < n; i++) atomicAdd(&g_deg[e[E + base + i]], 1);
        }
    }
}

// ---------------------------------------------------------------------------
// K2: dinv, dropout1(x) via precomputed mask, p1 = keep * x * 2.5 * dinv.
__global__ void k_node1(const float* __restrict__ x, int N) {
    int n = blockIdx.x * blockDim.x + threadIdx.x;
    if (n >= N) return;
    int di = g_deg[n];
    float d = di > 0 ? rsqrtf((float)di) : 0.f;
    g_dinv[n] = d;
    bool keep = (g_mask1[n >> 5] >> (n & 31)) & 1u;
    g_p1[n] = keep ? x[n] * (INV_KEEP * d) : 0.f;
}

// ---------------------------------------------------------------------------
// K3: layer-1 edge scatter with bitmask pre-filter. 8 edges/thread.
__global__ void __launch_bounds__(256) k_edge1(const void* __restrict__ eiv, long long E) {
    long long base = 8LL * (blockIdx.x * (long long)blockDim.x + threadIdx.x);
    if (base >= E) return;
    int is64 = g_is64;
    if (base + 8 <= E) {
        int srcs[8], dsts[8];
        load8(eiv, base, is64, srcs);
        load8(eiv, E + base, is64, dsts);
        unsigned keep = 0;
        #pragma unroll
        for (int i = 0; i < 8; i++) {
            unsigned w = g_mask1[srcs[i] >> 5];
            keep |= ((w >> (srcs[i] & 31)) & 1u) << i;
        }
        #pragma unroll
        for (int i = 0; i < 8; i++) {
            if ((keep >> i) & 1u) {
                float v = __ldg(&g_p1[srcs[i]]);
                atomicAdd(&g_acc1[dsts[i]], v);
            }
        }
    } else {
        int n = (int)(E - base);
        for (int i = 0; i < n; i++) {
            int s, d;
            if (is64) {
                const long long* e = (const long long*)eiv;
                s = (int)e[base + i]; d = (int)e[E + base + i];
            } else {
                const int* e = (const int*)eiv;
                s = e[base + i]; d = e[E + base + i];
            }
            if ((g_mask1[s >> 5] >> (s & 31)) & 1u)
                atomicAdd(&g_acc1[d], g_p1[s]);
        }
    }
}

// ---------------------------------------------------------------------------
// K4: layer-1 epilogue + dropout2 (precomputed bits) + layer-2 linear.
__global__ void k_node2(const float* __restrict__ W1, const float* __restrict__ B1,
                        const float* __restrict__ W2, int N) {
    __shared__ float w1[16], b1s[16], w2[16];
    if (threadIdx.x < 16) {
        w1[threadIdx.x] = W1[threadIdx.x];
        b1s[threadIdx.x] = B1[threadIdx.x];
        w2[threadIdx.x] = W2[threadIdx.x];
    }
    __syncthreads();
    int n = blockIdx.x * blockDim.x + threadIdx.x;
    if (n >= N) return;
    float dv = g_dinv[n];
    float a = g_acc1[n] * dv;
    unsigned word = g_mask2[n >> 1];
    unsigned m = (word >> ((n & 1) * 16)) & 0xFFFFu;
    float s = 0.f;
    while (m) {
        int c = __ffs(m) - 1;
        m &= m - 1;
        float v = fmaf(a, w1[c], b1s[c]);
        if (v > 0.f) s += v * w2[c];
    }
    g_p2[n] = s * INV_KEEP * dv;
}

// ---------------------------------------------------------------------------
// K5: layer-2 edge scatter (skip exact zeros). 8 edges/thread.
__global__ void __launch_bounds__(256) k_edge2(const void* __restrict__ eiv, long long E) {
    long long base = 8LL * (blockIdx.x * (long long)blockDim.x + threadIdx.x);
    if (base >= E) return;
    int is64 = g_is64;
    if (base + 8 <= E) {
        int srcs[8], dsts[8];
        load8(eiv, base, is64, srcs);
        load8(eiv, E + base, is64, dsts);
        float v[8];
        #pragma unroll
        for (int i = 0; i < 8; i++) v[i] = __ldg(&g_p2[srcs[i]]);
        #pragma unroll
        for (int i = 0; i < 8; i++)
            if (v[i] != 0.f) atomicAdd(&g_acc2[dsts[i]], v[i]);
    } else {
        int n = (int)(E - base);
        for (int i = 0; i < n; i++) {
            int s, d;
            if (is64) {
                const long long* e = (const long long*)eiv;
                s = (int)e[base + i]; d = (int)e[E + base + i];
            } else {
                const int* e = (const int*)eiv;
                s = e[base + i]; d = e[E + base + i];
            }
            float v = g_p2[s];
            if (v != 0.f) atomicAdd(&g_acc2[d], v);
        }
    }
}

// ---------------------------------------------------------------------------
// K6: final output.
__global__ void k_out(float* __restrict__ out, const float* __restrict__ B2, int N) {
    int n = blockIdx.x * blockDim.x + threadIdx.x;
    if (n < N) out[n] = g_acc2[n] * g_dinv[n] + B2[0];
}

// ---------------------------------------------------------------------------
extern "C" void kernel_launch(void* const* d_in, const int* in_sizes, int n_in,
                              void* d_out, int out_size) {
    const float* x  = (const float*)d_in[0];
    const void*  ei = d_in[1];
    const float* W1 = (const float*)d_in[2];
    const float* B1 = (const float*)d_in[3];
    const float* W2 = (const float*)d_in[4];
    const float* B2 = (const float*)d_in[5];
    int N = in_sizes[0];
    long long E = (long long)in_sizes[1] / 2;
    if (N > MAXN) return;

    // Side stream + events for deg || rng overlap (created once; graph
    // capture records the fork/join as graph edges).
    static cudaStream_t s1 = nullptr;
    static cudaEvent_t evFork = nullptr, evJoin = nullptr;
    if (!s1) {
        cudaStreamCreateWithFlags(&s1, cudaStreamNonBlocking);
        cudaEventCreateWithFlags(&evFork, cudaEventDisableTiming);
        cudaEventCreateWithFlags(&evJoin, cudaEventDisableTiming);
    }

    uint32_t k1a, k1b, k2a, k2b;
    tf2x32(0u, 42u, 0u, 0u, k1a, k1b);
    tf2x32(0u, 42u, 0u, 1u, k2a, k2b);

    long long nvec = (E + 7) / 8;
    int eb = (int)((nvec + 255) / 256);
    long long rng_threads = (16LL * N + 1) / 2;   // 2 mask2 bits + 1 mask1 bit / thread
    int rb = (int)((rng_threads + 255) / 256);

    k_init<<<(N + 255) / 256, 256>>>((const unsigned int*)ei, N, (long long)in_sizes[1]);

    // fork: rng on s1 concurrent with deg on main stream
    cudaEventRecord(evFork, 0);
    cudaStreamWaitEvent(s1, evFork, 0);
    k_rng<<<rb, 256, 0, s1>>>(N, k1a, k1b, k2a, k2b);
    cudaEventRecord(evJoin, s1);

    k_deg<<<eb, 256>>>(ei, E);
    cudaStreamWaitEvent(0, evJoin, 0);   // join before node1 (needs mask1)

    k_node1<<<(N + 255) / 256, 256>>>(x, N);
    k_edge1<<<eb, 256>>>(ei, E);
    k_node2<<<(N + 255) / 256, 256>>>(W1, B1, W2, N);
    k_edge2<<<eb, 256>>>(ei, E);
    k_out<<<(N + 255) / 256, 256>>>((float*)d_out, B2, N);
}

// round 11
// speedup vs baseline: 1.0175x; 1.0175x over previous
#include <cuda_runtime.h>
#include <cstdint>

// ---------------------------------------------------------------------------
// GCN_8796093022507: 2-layer GCN collapsed to scalar edge aggregations.
// Dropout = JAX threefry2x32 partitionable path: bits(i) = o0^o1 of
// tf(key,(0,i)); foldlike split: key_j = tf(parent,(0,j)).
// R11: single stream; RNG fused into k_init; acc zeroing moved into node
// kernels; node/out kernels vectorized for ILP; lean deg/edge kernels.
// ---------------------------------------------------------------------------

#define MAXN 100352
#define KEEP_TH 0x66666800u   // bits < TH  <=>  uniform(bits) < 0.4f
#define INV_KEEP 2.5f         // 1/(1-0.6)

__device__ int      g_deg[MAXN];
__device__ float    g_dinv[MAXN];
__device__ float    g_p1[MAXN];
__device__ float    g_acc1[MAXN];
__device__ float    g_p2[MAXN];
__device__ float    g_acc2[MAXN];
__device__ unsigned g_mask1[MAXN / 32 + 2];   // dropout1 keep bits, node n -> bit n
__device__ unsigned g_mask2[MAXN / 2 + 2];    // dropout2 keep bits, element 16n+c
__device__ int      g_is64;

__host__ __device__ __forceinline__ uint32_t rotl32(uint32_t v, int r) {
#ifdef __CUDA_ARCH__
    return __funnelshift_l(v, v, r);
#else
    return (v << r) | (v >> (32 - r));
#endif
}

__host__ __device__ __forceinline__ void tf2x32(uint32_t k0, uint32_t k1,
                                                uint32_t x0, uint32_t x1,
                                                uint32_t& o0, uint32_t& o1) {
    const uint32_t k2 = k0 ^ k1 ^ 0x1BD11BDAu;
    x0 += k0; x1 += k1;
#define TFR(r) { x0 += x1; x1 = rotl32(x1, r); x1 ^= x0; }
    TFR(13) TFR(15) TFR(26) TFR(6)
    x0 += k1; x1 += k2 + 1u;
    TFR(17) TFR(29) TFR(16) TFR(24)
    x0 += k2; x1 += k0 + 2u;
    TFR(13) TFR(15) TFR(26) TFR(6)
    x0 += k0; x1 += k1 + 3u;
    TFR(17) TFR(29) TFR(16) TFR(24)
    x0 += k1; x1 += k2 + 4u;
    TFR(13) TFR(15) TFR(26) TFR(6)
    o0 = x0 + k2; o1 = x1 + k0 + 5u;
#undef TFR
}

__device__ __forceinline__ uint32_t rbits32(uint32_t k0, uint32_t k1, uint32_t i) {
    uint32_t o0, o1;
    tf2x32(k0, k1, 0u, i, o0, o1);
    return o0 ^ o1;
}

// ---------------------------------------------------------------------------
// K0: RNG masks + zero g_deg + detect index dtype. Grid covers RNG work
// (16N/64 warps); first N threads also zero g_deg.
//   mask2: warp gw covers elements [64gw, 64gw+64): lane l -> 64gw+l and
//          64gw+32+l; two ballots = words 2gw, 2gw+1 (element e -> bit e&31).
//   mask1: lane l of warp gw -> node 32gw+l -> word gw.
__global__ void __launch_bounds__(256) k_init(const unsigned int* __restrict__ ei32,
                                              int N, long long nwords,
                                              uint32_t k1a, uint32_t k1b,
                                              uint32_t k2a, uint32_t k2b) {
    long long t = blockIdx.x * (long long)blockDim.x + threadIdx.x;
    int lane = threadIdx.x & 31;
    long long wbase = (t - lane) * 2;    // 64 * global_warp_id
    long long TE = 16LL * N;
    long long e0 = wbase + lane, e1 = wbase + 32 + lane;
    bool kp0 = (e0 < TE) && rbits32(k2a, k2b, (uint32_t)e0) < KEEP_TH;
    bool kp1 = (e1 < TE) && rbits32(k2a, k2b, (uint32_t)e1) < KEEP_TH;
    unsigned w0 = __ballot_sync(0xFFFFFFFFu, kp0);
    unsigned w1 = __ballot_sync(0xFFFFFFFFu, kp1);
    bool kpn = (t < N) && rbits32(k1a, k1b, (uint32_t)t) < KEEP_TH;
    unsigned wn = __ballot_sync(0xFFFFFFFFu, kpn);
    if (lane == 0) {
        if (wbase < TE)      g_mask2[(int)(wbase >> 5)]     = w0;
        if (wbase + 32 < TE) g_mask2[(int)(wbase >> 5) + 1] = w1;
        if (t < N)           g_mask1[(int)(t >> 5)]         = wn;
    }
    if (t < N) g_deg[(int)t] = 0;

    if (blockIdx.x == 0) {
        unsigned int v = 0;
        #pragma unroll
        for (int k = 0; k < 8; k++) {
            long long w = 1 + 2LL * (threadIdx.x * 8 + k);
            if (w < nwords) v |= ei32[w];
        }
        int nz = __syncthreads_or(v != 0);
        if (threadIdx.x == 0) g_is64 = nz ? 0 : 1;
    }
}

// ---------------------------------------------------------------------------
// Load 8 consecutive indices at element offset `off` (8-aligned).
__device__ __forceinline__ void load8(const void* eiv, long long off, int is64,
                                      int* out) {
    if (is64) {
        const longlong2* e = (const longlong2*)((const long long*)eiv + off);
        #pragma unroll
        for (int k = 0; k < 4; k++) {
            longlong2 d = e[k];
            out[2 * k] = (int)d.x; out[2 * k + 1] = (int)d.y;
        }
    } else {
        const int4* e = (const int4*)((const int*)eiv + off);
        int4 a = e[0], b = e[1];
        out[0] = a.x; out[1] = a.y; out[2] = a.z; out[3] = a.w;
        out[4] = b.x; out[5] = b.y; out[6] = b.z; out[7] = b.w;
    }
}

// ---------------------------------------------------------------------------
// K1: in-degree at dst. 8 edges/thread, lean.
__global__ void __launch_bounds__(256) k_deg(const void* __restrict__ eiv, long long E) {
    long long base = 8LL * (blockIdx.x * (long long)blockDim.x + threadIdx.x);
    if (base >= E) return;
    int is64 = g_is64;
    if (base + 8 <= E) {
        int dsts[8];
        load8(eiv, E + base, is64, dsts);
        #pragma unroll
        for (int i = 0; i < 8; i++) atomicAdd(&g_deg[dsts[i]], 1);
    } else {
        int n = (int)(E - base);
        if (is64) {
            const long long* e = (const long long*)eiv;
            for (int i = 0; i < n; i++) atomicAdd(&g_deg[(int)e[E + base + i]], 1);
        } else {
            const int* e = (const int*)eiv;
            for (int i = 0; i < n; i++) atomicAdd(&g_deg[e[E + base + i]], 1);
        }
    }
}

// ---------------------------------------------------------------------------
// K2: dinv, dropout1(x), p1 = keep * x * 2.5 * dinv, zero acc1.
//     4 nodes/thread, vectorized.
__global__ void __launch_bounds__(256) k_node1(const float* __restrict__ x, int N) {
    int j = (blockIdx.x * blockDim.x + threadIdx.x) * 4;
    if (j + 4 <= N) {
        int4 dg = *(const int4*)&g_deg[j];
        float4 xv = *(const float4*)&x[j];
        unsigned mw = g_mask1[j >> 5] >> (j & 31);   // 4 consecutive bits
        float d0 = dg.x > 0 ? rsqrtf((float)dg.x) : 0.f;
        float d1 = dg.y > 0 ? rsqrtf((float)dg.y) : 0.f;
        float d2 = dg.z > 0 ? rsqrtf((float)dg.z) : 0.f;
        float d3 = dg.w > 0 ? rsqrtf((float)dg.w) : 0.f;
        *(float4*)&g_dinv[j] = make_float4(d0, d1, d2, d3);
        float4 p;
        p.x = (mw & 1u) ? xv.x * (INV_KEEP * d0) : 0.f;
        p.y = (mw & 2u) ? xv.y * (INV_KEEP * d1) : 0.f;
        p.z = (mw & 4u) ? xv.z * (INV_KEEP * d2) : 0.f;
        p.w = (mw & 8u) ? xv.w * (INV_KEEP * d3) : 0.f;
        *(float4*)&g_p1[j] = p;
        *(float4*)&g_acc1[j] = make_float4(0.f, 0.f, 0.f, 0.f);
    } else {
        for (int n = j; n < N; n++) {
            int di = g_deg[n];
            float d = di > 0 ? rsqrtf((float)di) : 0.f;
            g_dinv[n] = d;
            bool keep = (g_mask1[n >> 5] >> (n & 31)) & 1u;
            g_p1[n] = keep ? x[n] * (INV_KEEP * d) : 0.f;
            g_acc1[n] = 0.f;
        }
    }
}

// ---------------------------------------------------------------------------
// K3: layer-1 edge scatter with bitmask pre-filter. 8 edges/thread.
__global__ void __launch_bounds__(256) k_edge1(const void* __restrict__ eiv, long long E) {
    long long base = 8LL * (blockIdx.x * (long long)blockDim.x + threadIdx.x);
    if (base >= E) return;
    int is64 = g_is64;
    if (base + 8 <= E) {
        int srcs[8], dsts[8];
        load8(eiv, base, is64, srcs);
        load8(eiv, E + base, is64, dsts);
        unsigned keep = 0;
        #pragma unroll
        for (int i = 0; i < 8; i++) {
            unsigned w = g_mask1[srcs[i] >> 5];
            keep |= ((w >> (srcs[i] & 31)) & 1u) << i;
        }
        #pragma unroll
        for (int i = 0; i < 8; i++) {
            if ((keep >> i) & 1u) {
                float v = __ldg(&g_p1[srcs[i]]);
                atomicAdd(&g_acc1[dsts[i]], v);
            }
        }
    } else {
        int n = (int)(E - base);
        for (int i = 0; i < n; i++) {
            int s, d;
            if (is64) {
                const long long* e = (const long long*)eiv;
                s = (int)e[base + i]; d = (int)e[E + base + i];
            } else {
                const int* e = (const int*)eiv;
                s = e[base + i]; d = e[E + base + i];
            }
            if ((g_mask1[s >> 5] >> (s & 31)) & 1u)
                atomicAdd(&g_acc1[d], g_p1[s]);
        }
    }
}

// ---------------------------------------------------------------------------
// K4: layer-1 epilogue + dropout2 (precomputed bits) + layer-2 linear,
//     zero acc2. 2 nodes/thread; one mask2 word covers exactly the pair.
__global__ void __launch_bounds__(256) k_node2(const float* __restrict__ W1,
                                               const float* __restrict__ B1,
                                               const float* __restrict__ W2, int N) {
    __shared__ float w1[16], b1s[16], w2[16];
    if (threadIdx.x < 16) {
        w1[threadIdx.x] = W1[threadIdx.x];
        b1s[threadIdx.x] = B1[threadIdx.x];
        w2[threadIdx.x] = W2[threadIdx.x];
    }
    __syncthreads();
    int j = (blockIdx.x * blockDim.x + threadIdx.x) * 2;
    if (j >= N) return;
    if (j + 2 <= N) {
        float2 dv = *(const float2*)&g_dinv[j];
        float2 ac = *(const float2*)&g_acc1[j];
        unsigned word = g_mask2[j >> 1];
        float a0 = ac.x * dv.x, a1 = ac.y * dv.y;
        unsigned m0 = word & 0xFFFFu, m1 = word >> 16;
        float s0 = 0.f, s1 = 0.f;
        while (m0) {
            int c = __ffs(m0) - 1; m0 &= m0 - 1;
            float v = fmaf(a0, w1[c], b1s[c]);
            if (v > 0.f) s0 += v * w2[c];
        }
        while (m1) {
            int c = __ffs(m1) - 1; m1 &= m1 - 1;
            float v = fmaf(a1, w1[c], b1s[c]);
            if (v > 0.f) s1 += v * w2[c];
        }
        *(float2*)&g_p2[j] = make_float2(s0 * INV_KEEP * dv.x, s1 * INV_KEEP * dv.y);
        *(float2*)&g_acc2[j] = make_float2(0.f, 0.f);
    } else {
        int n = j;
        float dv = g_dinv[n];
        float a = g_acc1[n] * dv;
        unsigned m = (g_mask2[n >> 1] >> ((n & 1) * 16)) & 0xFFFFu;
        float s = 0.f;
        while (m) {
            int c = __ffs(m) - 1; m &= m - 1;
            float v = fmaf(a, w1[c], b1s[c]);
            if (v > 0.f) s += v * w2[c];
        }
        g_p2[n] = s * INV_KEEP * dv;
        g_acc2[n] = 0.f;
    }
}

// ---------------------------------------------------------------------------
// K5: layer-2 edge scatter (skip exact zeros). 8 edges/thread.
__global__ void __launch_bounds__(256) k_edge2(const void* __restrict__ eiv, long long E) {
    long long base = 8LL * (blockIdx.x * (long long)blockDim.x + threadIdx.x);
    if (base >= E) return;
    int is64 = g_is64;
    if (base + 8 <= E) {
        int srcs[8], dsts[8];
        load8(eiv, base, is64, srcs);
        load8(eiv, E + base, is64, dsts);
        float v[8];
        #pragma unroll
        for (int i = 0; i < 8; i++) v[i] = __ldg(&g_p2[srcs[i]]);
        #pragma unroll
        for (int i = 0; i < 8; i++)
            if (v[i] != 0.f) atomicAdd(&g_acc2[dsts[i]], v[i]);
    } else {
        int n = (int)(E - base);
        for (int i = 0; i < n; i++) {
            int s, d;
            if (is64) {
                const long long* e = (const long long*)eiv;
                s = (int)e[base + i]; d = (int)e[E + base + i];
            } else {
                const int* e = (const int*)eiv;
                s = e[base + i]; d = e[E + base + i];
            }
            float v = g_p2[s];
            if (v != 0.f) atomicAdd(&g_acc2[d], v);
        }
    }
}

// ---------------------------------------------------------------------------
// K6: final output, 4 nodes/thread.
__global__ void __launch_bounds__(256) k_out(float* __restrict__ out,
                                             const float* __restrict__ B2, int N) {
    int j = (blockIdx.x * blockDim.x + threadIdx.x) * 4;
    float b = B2[0];
    if (j + 4 <= N) {
        float4 ac = *(const float4*)&g_acc2[j];
        float4 dv = *(const float4*)&g_dinv[j];
        float4 o;
        o.x = ac.x * dv.x + b;
        o.y = ac.y * dv.y + b;
        o.z = ac.z * dv.z + b;
        o.w = ac.w * dv.w + b;
        *(float4*)&out[j] = o;
    } else {
        for (int n = j; n < N; n++) out[n] = g_acc2[n] * g_dinv[n] + b;
    }
}

// ---------------------------------------------------------------------------
extern "C" void kernel_launch(void* const* d_in, const int* in_sizes, int n_in,
                              void* d_out, int out_size) {
    const float* x  = (const float*)d_in[0];
    const void*  ei = d_in[1];
    const float* W1 = (const float*)d_in[2];
    const float* B1 = (const float*)d_in[3];
    const float* W2 = (const float*)d_in[4];
    const float* B2 = (const float*)d_in[5];
    int N = in_sizes[0];
    long long E = (long long)in_sizes[1] / 2;
    if (N > MAXN) return;

    uint32_t k1a, k1b, k2a, k2b;
    tf2x32(0u, 42u, 0u, 0u, k1a, k1b);
    tf2x32(0u, 42u, 0u, 1u, k2a, k2b);

    long long nvec = (E + 7) / 8;
    int eb = (int)((nvec + 255) / 256);
    long long rng_threads = (16LL * N + 1) / 2;   // 2 mask2 bits/thread
    if (rng_threads < N) rng_threads = N;
    int ib = (int)((rng_threads + 255) / 256);

    k_init<<<ib, 256>>>((const unsigned int*)ei, N, (long long)in_sizes[1],
                        k1a, k1b, k2a, k2b);
    k_deg<<<eb, 256>>>(ei, E);
    k_node1<<<(N / 4 + 255) / 256 + 1, 256>>>(x, N);
    k_edge1<<<eb, 256>>>(ei, E);
    k_node2<<<(N / 2 + 255) / 256 + 1, 256>>>(W1, B1, W2, N);
    k_edge2<<<eb, 256>>>(ei, E);
    k_out<<<(N / 4 + 255) / 256 + 1, 256>>>((float*)d_out, B2, N);
}

// round 13
// speedup vs baseline: 1.0296x; 1.0119x over previous
#include <cuda_runtime.h>
#include <cstdint>

// ---------------------------------------------------------------------------
// GCN_8796093022507: 2-layer GCN collapsed to scalar edge aggregations.
// Dropout = JAX threefry2x32 partitionable path: bits(i) = o0^o1 of
// tf(key,(0,i)); foldlike split: key_j = tf(parent,(0,j)).
// R12: R8 structure (RNG fused into memory-bound deg pass = best measured)
// + R11 vectorized node/out kernels + slim init (acc zeroing in node
// kernels). Edge kernels at the per-SM REDG-issue floor.
// ---------------------------------------------------------------------------

#define MAXN 100352
#define KEEP_TH 0x66666800u   // bits < TH  <=>  uniform(bits) < 0.4f
#define INV_KEEP 2.5f         // 1/(1-0.6)

__device__ int      g_deg[MAXN];
__device__ float    g_dinv[MAXN];
__device__ float    g_p1[MAXN];
__device__ float    g_acc1[MAXN];
__device__ float    g_p2[MAXN];
__device__ float    g_acc2[MAXN];
__device__ unsigned g_mask1[MAXN / 32 + 2];   // dropout1 keep bits, node n -> bit n
__device__ unsigned g_mask2[MAXN / 2 + 2];    // dropout2 keep bits, element 16n+c
__device__ int      g_is64;

__host__ __device__ __forceinline__ uint32_t rotl32(uint32_t v, int r) {
#ifdef __CUDA_ARCH__
    return __funnelshift_l(v, v, r);
#else
    return (v << r) | (v >> (32 - r));
#endif
}

__host__ __device__ __forceinline__ void tf2x32(uint32_t k0, uint32_t k1,
                                                uint32_t x0, uint32_t x1,
                                                uint32_t& o0, uint32_t& o1) {
    const uint32_t k2 = k0 ^ k1 ^ 0x1BD11BDAu;
    x0 += k0; x1 += k1;
#define TFR(r) { x0 += x1; x1 = rotl32(x1, r); x1 ^= x0; }
    TFR(13) TFR(15) TFR(26) TFR(6)
    x0 += k1; x1 += k2 + 1u;
    TFR(17) TFR(29) TFR(16) TFR(24)
    x0 += k2; x1 += k0 + 2u;
    TFR(13) TFR(15) TFR(26) TFR(6)
    x0 += k0; x1 += k1 + 3u;
    TFR(17) TFR(29) TFR(16) TFR(24)
    x0 += k1; x1 += k2 + 4u;
    TFR(13) TFR(15) TFR(26) TFR(6)
    o0 = x0 + k2; o1 = x1 + k0 + 5u;
#undef TFR
}

__device__ __forceinline__ uint32_t rbits32(uint32_t k0, uint32_t k1, uint32_t i) {
    uint32_t o0, o1;
    tf2x32(k0, k1, 0u, i, o0, o1);
    return o0 ^ o1;
}

// ---------------------------------------------------------------------------
// K0: zero g_deg + detect index dtype (int64 <=> all odd 32-bit words zero).
__global__ void __launch_bounds__(256) k_init(const unsigned int* __restrict__ ei32,
                                              int N, long long nwords) {
    int n = blockIdx.x * blockDim.x + threadIdx.x;
    if (n < N) g_deg[n] = 0;
    if (blockIdx.x == 0) {
        unsigned int v = 0;
        #pragma unroll
        for (int k = 0; k < 8; k++) {
            long long w = 1 + 2LL * (threadIdx.x * 8 + k);
            if (w < nwords) v |= ei32[w];
        }
        int nz = __syncthreads_or(v != 0);
        if (threadIdx.x == 0) g_is64 = nz ? 0 : 1;
    }
}

// ---------------------------------------------------------------------------
// Load 8 consecutive indices at element offset `off` (8-aligned).
__device__ __forceinline__ void load8(const void* eiv, long long off, int is64,
                                      int* out) {
    if (is64) {
        const longlong2* e = (const longlong2*)((const long long*)eiv + off);
        #pragma unroll
        for (int k = 0; k < 4; k++) {
            longlong2 d = e[k];
            out[2 * k] = (int)d.x; out[2 * k + 1] = (int)d.y;
        }
    } else {
        const int4* e = (const int4*)((const int*)eiv + off);
        int4 a = e[0], b = e[1];
        out[0] = a.x; out[1] = a.y; out[2] = a.z; out[3] = a.w;
        out[4] = b.x; out[5] = b.y; out[6] = b.z; out[7] = b.w;
    }
}

// ---------------------------------------------------------------------------
// K1: in-degree at dst (8 edges/thread) + ALL dropout RNG hidden under the
//     memory stalls (best measured placement, R8).
//   mask2: warp gw covers elements [64gw, 64gw+64): lane l -> 64gw+l and
//          64gw+32+l; two ballots = words 2gw, 2gw+1 (element e -> bit e&31).
//   mask1: lane l of warp gw -> node 32gw+l -> word gw.
__global__ void __launch_bounds__(256) k_deg(const void* __restrict__ eiv, long long E,
                                             int N,
                                             uint32_t k1a, uint32_t k1b,
                                             uint32_t k2a, uint32_t k2b) {
    long long t = blockIdx.x * (long long)blockDim.x + threadIdx.x;
    int lane = threadIdx.x & 31;

    // --- RNG section (independent ALU work) ---
    {
        long long wbase = (t - lane) * 2;     // 64 * global_warp_id
        long long TE = 16LL * N;
        long long e0 = wbase + lane, e1 = wbase + 32 + lane;
        bool kp0 = (e0 < TE) && rbits32(k2a, k2b, (uint32_t)e0) < KEEP_TH;
        bool kp1 = (e1 < TE) && rbits32(k2a, k2b, (uint32_t)e1) < KEEP_TH;
        unsigned w0 = __ballot_sync(0xFFFFFFFFu, kp0);
        unsigned w1 = __ballot_sync(0xFFFFFFFFu, kp1);
        bool kpn = (t < N) && rbits32(k1a, k1b, (uint32_t)t) < KEEP_TH;
        unsigned wn = __ballot_sync(0xFFFFFFFFu, kpn);
        if (lane == 0) {
            if (wbase < TE)      g_mask2[(int)(wbase >> 5)]     = w0;
            if (wbase + 32 < TE) g_mask2[(int)(wbase >> 5) + 1] = w1;
            if (t < N)           g_mask1[(int)(t >> 5)]         = wn;
        }
    }

    // --- degree section ---
    long long base = 8LL * t;
    if (base >= E) return;
    int is64 = g_is64;
    if (base + 8 <= E) {
        int dsts[8];
        load8(eiv, E + base, is64, dsts);
        #pragma unroll
        for (int i = 0; i < 8; i++) atomicAdd(&g_deg[dsts[i]], 1);
    } else {
        int n = (int)(E - base);
        if (is64) {
            const long long* e = (const long long*)eiv;
            for (int i = 0; i < n; i++) atomicAdd(&g_deg[(int)e[E + base + i]], 1);
        } else {
            const int* e = (const int*)eiv;
            for (int i = 0; i < n; i++) atomicAdd(&g_deg[e[E + base + i]], 1);
        }
    }
}

// ---------------------------------------------------------------------------
// K2: dinv, dropout1(x), p1 = keep * x * 2.5 * dinv, zero acc1.
//     4 nodes/thread, vectorized.
__global__ void __launch_bounds__(256) k_node1(const float* __restrict__ x, int N) {
    int j = (blockIdx.x * blockDim.x + threadIdx.x) * 4;
    if (j + 4 <= N) {
        int4 dg = *(const int4*)&g_deg[j];
        float4 xv = *(const float4*)&x[j];
        unsigned mw = g_mask1[j >> 5] >> (j & 31);   // 4 consecutive bits
        float d0 = dg.x > 0 ? rsqrtf((float)dg.x) : 0.f;
        float d1 = dg.y > 0 ? rsqrtf((float)dg.y) : 0.f;
        float d2 = dg.z > 0 ? rsqrtf((float)dg.z) : 0.f;
        float d3 = dg.w > 0 ? rsqrtf((float)dg.w) : 0.f;
        *(float4*)&g_dinv[j] = make_float4(d0, d1, d2, d3);
        float4 p;
        p.x = (mw & 1u) ? xv.x * (INV_KEEP * d0) : 0.f;
        p.y = (mw & 2u) ? xv.y * (INV_KEEP * d1) : 0.f;
        p.z = (mw & 4u) ? xv.z * (INV_KEEP * d2) : 0.f;
        p.w = (mw & 8u) ? xv.w * (INV_KEEP * d3) : 0.f;
        *(float4*)&g_p1[j] = p;
        *(float4*)&g_acc1[j] = make_float4(0.f, 0.f, 0.f, 0.f);
    } else {
        for (int n = j; n < N; n++) {
            int di = g_deg[n];
            float d = di > 0 ? rsqrtf((float)di) : 0.f;
            g_dinv[n] = d;
            bool keep = (g_mask1[n >> 5] >> (n & 31)) & 1u;
            g_p1[n] = keep ? x[n] * (INV_KEEP * d) : 0.f;
            g_acc1[n] = 0.f;
        }
    }
}

// ---------------------------------------------------------------------------
// K3: layer-1 edge scatter with bitmask pre-filter. 8 edges/thread.
__global__ void __launch_bounds__(256) k_edge1(const void* __restrict__ eiv, long long E) {
    long long base = 8LL * (blockIdx.x * (long long)blockDim.x + threadIdx.x);
    if (base >= E) return;
    int is64 = g_is64;
    if (base + 8 <= E) {
        int srcs[8], dsts[8];
        load8(eiv, base, is64, srcs);
        load8(eiv, E + base, is64, dsts);
        unsigned keep = 0;
        #pragma unroll
        for (int i = 0; i < 8; i++) {
            unsigned w = g_mask1[srcs[i] >> 5];
            keep |= ((w >> (srcs[i] & 31)) & 1u) << i;
        }
        #pragma unroll
        for (int i = 0; i < 8; i++) {
            if ((keep >> i) & 1u) {
                float v = __ldg(&g_p1[srcs[i]]);
                atomicAdd(&g_acc1[dsts[i]], v);
            }
        }
    } else {
        int n = (int)(E - base);
        for (int i = 0; i < n; i++) {
            int s, d;
            if (is64) {
                const long long* e = (const long long*)eiv;
                s = (int)e[base + i]; d = (int)e[E + base + i];
            } else {
                const int* e = (const int*)eiv;
                s = e[base + i]; d = e[E + base + i];
            }
            if ((g_mask1[s >> 5] >> (s & 31)) & 1u)
                atomicAdd(&g_acc1[d], g_p1[s]);
        }
    }
}

// ---------------------------------------------------------------------------
// K4: layer-1 epilogue + dropout2 (precomputed bits) + layer-2 linear,
//     zero acc2. 2 nodes/thread; one mask2 word covers exactly the pair.
__global__ void __launch_bounds__(256) k_node2(const float* __restrict__ W1,
                                               const float* __restrict__ B1,
                                               const float* __restrict__ W2, int N) {
    __shared__ float w1[16], b1s[16], w2[16];
    if (threadIdx.x < 16) {
        w1[threadIdx.x] = W1[threadIdx.x];
        b1s[threadIdx.x] = B1[threadIdx.x];
        w2[threadIdx.x] = W2[threadIdx.x];
    }
    __syncthreads();
    int j = (blockIdx.x * blockDim.x + threadIdx.x) * 2;
    if (j >= N) return;
    if (j + 2 <= N) {
        float2 dv = *(const float2*)&g_dinv[j];
        float2 ac = *(const float2*)&g_acc1[j];
        unsigned word = g_mask2[j >> 1];
        float a0 = ac.x * dv.x, a1 = ac.y * dv.y;
        unsigned m0 = word & 0xFFFFu, m1 = word >> 16;
        float s0 = 0.f, s1 = 0.f;
        while (m0) {
            int c = __ffs(m0) - 1; m0 &= m0 - 1;
            float v = fmaf(a0, w1[c], b1s[c]);
            if (v > 0.f) s0 += v * w2[c];
        }
        while (m1) {
            int c = __ffs(m1) - 1; m1 &= m1 - 1;
            float v = fmaf(a1, w1[c], b1s[c]);
            if (v > 0.f) s1 += v * w2[c];
        }
        *(float2*)&g_p2[j] = make_float2(s0 * INV_KEEP * dv.x, s1 * INV_KEEP * dv.y);
        *(float2*)&g_acc2[j] = make_float2(0.f, 0.f);
    } else {
        int n = j;
        float dv = g_dinv[n];
        float a = g_acc1[n] * dv;
        unsigned m = (g_mask2[n >> 1] >> ((n & 1) * 16)) & 0xFFFFu;
        float s = 0.f;
        while (m) {
            int c = __ffs(m) - 1; m &= m - 1;
            float v = fmaf(a, w1[c], b1s[c]);
            if (v > 0.f) s += v * w2[c];
        }
        g_p2[n] = s * INV_KEEP * dv;
        g_acc2[n] = 0.f;
    }
}

// ---------------------------------------------------------------------------
// K5: layer-2 edge scatter (skip exact zeros). 8 edges/thread.
__global__ void __launch_bounds__(256) k_edge2(const void* __restrict__ eiv, long long E) {
    long long base = 8LL * (blockIdx.x * (long long)blockDim.x + threadIdx.x);
    if (base >= E) return;
    int is64 = g_is64;
    if (base + 8 <= E) {
        int srcs[8], dsts[8];
        load8(eiv, base, is64, srcs);
        load8(eiv, E + base, is64, dsts);
        float v[8];
        #pragma unroll
        for (int i = 0; i < 8; i++) v[i] = __ldg(&g_p2[srcs[i]]);
        #pragma unroll
        for (int i = 0; i < 8; i++)
            if (v[i] != 0.f) atomicAdd(&g_acc2[dsts[i]], v[i]);
    } else {
        int n = (int)(E - base);
        for (int i = 0; i < n; i++) {
            int s, d;
            if (is64) {
                const long long* e = (const long long*)eiv;
                s = (int)e[base + i]; d = (int)e[E + base + i];
            } else {
                const int* e = (const int*)eiv;
                s = e[base + i]; d = e[E + base + i];
            }
            float v = g_p2[s];
            if (v != 0.f) atomicAdd(&g_acc2[d], v);
        }
    }
}

// ---------------------------------------------------------------------------
// K6: final output, 4 nodes/thread.
__global__ void __launch_bounds__(256) k_out(float* __restrict__ out,
                                             const float* __restrict__ B2, int N) {
    int j = (blockIdx.x * blockDim.x + threadIdx.x) * 4;
    float b = B2[0];
    if (j + 4 <= N) {
        float4 ac = *(const float4*)&g_acc2[j];
        float4 dv = *(const float4*)&g_dinv[j];
        float4 o;
        o.x = ac.x * dv.x + b;
        o.y = ac.y * dv.y + b;
        o.z = ac.z * dv.z + b;
        o.w = ac.w * dv.w + b;
        *(float4*)&out[j] = o;
    } else {
        for (int n = j; n < N; n++) out[n] = g_acc2[n] * g_dinv[n] + b;
    }
}

// ---------------------------------------------------------------------------
extern "C" void kernel_launch(void* const* d_in, const int* in_sizes, int n_in,
                              void* d_out, int out_size) {
    const float* x  = (const float*)d_in[0];
    const void*  ei = d_in[1];
    const float* W1 = (const float*)d_in[2];
    const float* B1 = (const float*)d_in[3];
    const float* W2 = (const float*)d_in[4];
    const float* B2 = (const float*)d_in[5];
    int N = in_sizes[0];
    long long E = (long long)in_sizes[1] / 2;
    if (N > MAXN) return;

    uint32_t k1a, k1b, k2a, k2b;
    tf2x32(0u, 42u, 0u, 0u, k1a, k1b);
    tf2x32(0u, 42u, 0u, 1u, k2a, k2b);

    long long nvec = (E + 7) / 8;
    int eb = (int)((nvec + 255) / 256);
    // k_deg grid must also cover RNG: 2 mask2 bits + 1 mask1 bit per thread.
    long long rng_threads = (16LL * N + 1) / 2;
    if (rng_threads < N) rng_threads = N;
    int rb = (int)((rng_threads + 255) / 256);
    int db = eb > rb ? eb : rb;

    k_init<<<(N + 255) / 256, 256>>>((const unsigned int*)ei, N, (long long)in_sizes[1]);
    k_deg<<<db, 256>>>(ei, E, N, k1a, k1b, k2a, k2b);
    k_node1<<<(N / 4 + 255) / 256 + 1, 256>>>(x, N);
    k_edge1<<<eb, 256>>>(ei, E);
    k_node2<<<(N / 2 + 255) / 256 + 1, 256>>>(W1, B1, W2, N);
    k_edge2<<<eb, 256>>>(ei, E);
    k_out<<<(N / 4 + 255) / 256 + 1, 256>>>((float*)d_out, B2, N);
}